// round 14
// baseline (speedup 1.0000x reference)
#include <cuda_runtime.h>
#include <stdint.h>
#include <math.h>

#define CC    256
#define HH    256
#define WW    512
#define NPIX  (HH*WW)      // 131072
#define FH    256

// ---------------------------------------------------------------------------
// Device scratch (static — no allocations allowed)
// g_mp/g_auxp: u64 per pixel per group j = icc*8 + g, g = ks*4 + frag_p,
//   u64 = ( bf16x2 pair plo , bf16x2 pair plo+4 ), plo = icc*16 + ks*8 + frag_p
// ---------------------------------------------------------------------------
__device__ uint2    g_mp  [(size_t)64 * NPIX];    // m packed-interleaved (64MB)
__device__ uint2    g_auxp[(size_t)64 * NPIX];    // aux packed-interleaved (64MB)
__device__ uint32_t g_Wb  [2 * 72 * 2 * 16 * 32 * 2];  // bf16x2 frag-ordered (1.18MB)
__device__ float    g_logitM[NPIX];
__device__ int      g_face [NPIX];
__device__ int      g_off  [NPIX * 4];
__device__ float    g_gw   [NPIX * 4];

// ---------------------------------------------------------------------------
// helpers
// ---------------------------------------------------------------------------
__device__ __forceinline__ uint32_t smem_u32(const void* p) {
    uint32_t a;
    asm("{ .reg .u64 t; cvta.to.shared.u64 t, %1; cvt.u32.u64 %0, t; }" : "=r"(a) : "l"(p));
    return a;
}
__device__ __forceinline__ uint32_t pack_bf16x2(float hi, float lo) {
    uint32_t u;
    asm("cvt.rn.bf16x2.f32 %0, %1, %2;" : "=r"(u) : "f"(hi), "f"(lo));
    return u;
}
__device__ __forceinline__ uint2 lds64(uint32_t a) {
    uint2 r; asm volatile("ld.shared.v2.b32 {%0,%1}, [%2];" : "=r"(r.x), "=r"(r.y) : "r"(a));
    return r;
}
__device__ __forceinline__ void cp16z(uint32_t sdst, const void* gsrc, uint32_t sz) {
    asm volatile("cp.async.cg.shared.global [%0], [%1], 16, %2;"
                 :: "r"(sdst), "l"(gsrc), "r"(sz) : "memory");
}
#define CP_COMMIT() asm volatile("cp.async.commit_group;" ::: "memory")
#define CP_WAIT0()  asm volatile("cp.async.wait_group 0;" ::: "memory")
__device__ __forceinline__ void mma_bf16(float* d, const uint32_t* a, const uint32_t* b) {
    asm volatile(
        "mma.sync.aligned.m16n8k16.row.col.f32.bf16.bf16.f32 "
        "{%0,%1,%2,%3}, {%4,%5,%6,%7}, {%8,%9}, {%0,%1,%2,%3};"
        : "+f"(d[0]), "+f"(d[1]), "+f"(d[2]), "+f"(d[3])
        : "r"(a[0]), "r"(a[1]), "r"(a[2]), "r"(a[3]), "r"(b[0]), "r"(b[1]));
}
// group j -> low pair index
__device__ __forceinline__ int j_to_plo(int j) {
    int icc = j >> 3, g = j & 7, ks = g >> 2, fp = g & 3;
    return icc * 16 + ks * 8 + fp;
}

// ---------------------------------------------------------------------------
// 1) per-pixel cube2equi geometry
// ---------------------------------------------------------------------------
__global__ void geo_kernel() {
    int p = blockIdx.x * blockDim.x + threadIdx.x;
    if (p >= NPIX) return;
    int oy = p / WW, ox = p % WW;
    const float PI = 3.14159265358979323846f;
    float theta = ((ox + 0.5f) / (float)WW) * (2.0f * PI) - PI;
    float phi   = 0.5f * PI - ((oy + 0.5f) / (float)HH) * PI;
    float st = sinf(theta), ct = cosf(theta);
    float sp = sinf(phi),   cp = cosf(phi);
    float dx = cp * st, dy = sp, dz = cp * ct;
    float ax = fabsf(dx), ay = fabsf(dy), az = fabsf(dz);
    float mx = fmaxf(fmaxf(ax, ay), az);
    float px = dx / mx, py = dy / mx, pz = dz / mx;
    bool cz = (az >= ax) && (az >= ay);
    bool cx = (!cz) && (ax >= ay);
    int face = cz ? (dz > 0.f ? 2 : 0) : cx ? (dx > 0.f ? 4 : 3) : (dy > 0.f ? 5 : 1);
    float a  = cz ? (dz > 0.f ? px : -px) : cx ? (dx > 0.f ? -pz : pz) : px;
    float bc = (cz || cx) ? -py : (dy > 0.f ? pz : -pz);
    float uu = fminf(fmaxf((a  + 1.0f) * 0.5f * (float)(FH - 1), 0.0f), (float)(FH - 1));
    float vv = fminf(fmaxf((bc + 1.0f) * 0.5f * (float)(FH - 1), 0.0f), (float)(FH - 1));
    int u0 = (int)floorf(uu), v0 = (int)floorf(vv);
    int u1 = min(u0 + 1, FH - 1), v1 = min(v0 + 1, FH - 1);
    float wu = uu - (float)u0, wv = vv - (float)v0;
    g_face[p] = face;
    g_off[p*4+0] = v0 * FH + u0; g_off[p*4+1] = v0 * FH + u1;
    g_off[p*4+2] = v1 * FH + u0; g_off[p*4+3] = v1 * FH + u1;
    g_gw [p*4+0] = (1.f-wv)*(1.f-wu); g_gw[p*4+1] = (1.f-wv)*wu;
    g_gw [p*4+2] = wv*(1.f-wu);       g_gw[p*4+3] = wv*wu;
}

// ---------------------------------------------------------------------------
// 2a) pack m -> interleaved u64 groups: g_mp[j][p]
// ---------------------------------------------------------------------------
__global__ void packm_kernel(const float* __restrict__ m) {
    int idx = blockIdx.x * blockDim.x + threadIdx.x;
    if (idx >= 32 * NPIX) return;
    int p  = idx & (NPIX - 1);
    int jh = idx >> 17;                 // 0..31
#pragma unroll
    for (int k = 0; k < 2; k++) {
        const int j   = jh + k * 32;
        const int plo = j_to_plo(j);
        float a0 = m[(size_t)(2 * plo)     * NPIX + p];
        float a1 = m[(size_t)(2 * plo + 1) * NPIX + p];
        float b0 = m[(size_t)(2 * plo + 8) * NPIX + p];
        float b1 = m[(size_t)(2 * plo + 9) * NPIX + p];
        uint2 v;
        v.x = pack_bf16x2(a1, a0);
        v.y = pack_bf16x2(b1, b0);
        g_mp[(size_t)j * NPIX + p] = v;
    }
}

// ---------------------------------------------------------------------------
// 2b) aux = cube2equi(cube), interleaved u64 groups: g_auxp[j][p]
// ---------------------------------------------------------------------------
__global__ void aux_kernel(const float* __restrict__ fb, const float* __restrict__ fd,
                           const float* __restrict__ fu) {
    int idx = blockIdx.x * blockDim.x + threadIdx.x;
    if (idx >= 32 * NPIX) return;
    int p  = idx & (NPIX - 1);
    int jh = idx >> 17;                 // 0..31
    int f = g_face[p];
    const float* base = (f == 0) ? fb : (f == 1) ? fd : (f == 5) ? fu : nullptr;
    if (!base) {
        uint2 z; z.x = 0u; z.y = 0u;
        g_auxp[(size_t)jh        * NPIX + p] = z;
        g_auxp[(size_t)(jh + 32) * NPIX + p] = z;
        return;
    }
    const float4 gw = *(const float4*)&g_gw[p * 4];
    const int4   go = *(const int4*)&g_off[p * 4];
#pragma unroll
    for (int k = 0; k < 2; k++) {
        const int j   = jh + k * 32;
        const int plo = j_to_plo(j);
        float vv[4];
#pragma unroll
        for (int c = 0; c < 4; c++) {
            static const int offs[4] = {0, 1, 8, 9};
            const float* cp_ = base + (size_t)(2 * plo + offs[c]) * (FH * FH);
            vv[c] = gw.x*cp_[go.x] + gw.y*cp_[go.y] + gw.z*cp_[go.z] + gw.w*cp_[go.w];
        }
        uint2 v;
        v.x = pack_bf16x2(vv[1], vv[0]);
        v.y = pack_bf16x2(vv[3], vv[2]);
        g_auxp[(size_t)j * NPIX + p] = v;
    }
}

// ---------------------------------------------------------------------------
// 3) weights -> bf16x2 fragment order for m16n8k16 (layout validated in R7)
// ---------------------------------------------------------------------------
__global__ void wtb_kernel(const float* __restrict__ Wf) {
    int idx = blockIdx.x * blockDim.x + threadIdx.x;
    if (idx >= 2 * 72 * 2 * 16 * 32) return;
    int lane  = idx & 31;
    int ntile = (idx >> 5) & 15;
    int kstep = (idx >> 9) & 1;
    int qq    = idx >> 10;
    int q     = qq % 72;
    int half  = qq / 72;
    int icc = q / 9, tap = q % 9;
    int oc  = half * 128 + ntile * 8 + (lane >> 2);
    int ic  = icc * 32 + kstep * 16 + (lane & 3) * 2;
    const float* wp = Wf + (size_t)oc * CC * 9 + tap;
    float w0 = wp[(size_t)ic * 9];
    float w1 = wp[(size_t)(ic + 1) * 9];
    float w8 = wp[(size_t)(ic + 8) * 9];
    float w9 = wp[(size_t)(ic + 9) * 9];
    g_Wb[idx * 2 + 0] = pack_bf16x2(w1, w0);
    g_Wb[idx * 2 + 1] = pack_bf16x2(w9, w8);
}

// ---------------------------------------------------------------------------
// 4) bf16 mma.sync conv, 2 CTAs/SM, u64-interleaved A slab:
//    CTA = 64 px x 256 oc, 256 threads, 8 warps (1M x 8N); warp 64px x 32oc.
//    A: [g:8][ry:3][px:76] u64 per stage; 2 LDS.64 per mt (half the LDS of R12).
//    B: per-tap register LDG.64 from frag-ordered g_Wb.
// ---------------------------------------------------------------------------
#define PADXQ   76                       // u64 px pitch ; 6*76=456 == 8 mod 32 -> conflict-free
#define ASTAGE  (8 * 3 * PADXQ * 8)      // 14592 bytes per stage
#define SM_A     0
#define SM_BIAS  (2 * ASTAGE)            // 29184
#define SM_WM    (SM_BIAS + 1024)
#define SM_RED   (SM_WM + 1024)
#define SM_MASK  (SM_RED + 2048)
#define SMEM_SZ  (SM_MASK + 256)         // 33536

__global__ __launch_bounds__(256, 2)
void conv_mma(const uint2* __restrict__ inp,      // interleaved u64 [64][NPIX]
              const float* __restrict__ bias,
              const float* __restrict__ wm, float* __restrict__ outp,
              float* __restrict__ logit,
              const float* __restrict__ mres,     // non-null => fused final mode
              const float* __restrict__ logitM,
              const float* __restrict__ bmp)
{
    extern __shared__ char smem[];
    const uint32_t sb = smem_u32(smem);

    const int t    = threadIdx.x;
    const int w    = t >> 5;        // 0..7 : oc eighth (32 oc)
    const int lane = t & 31;

    const int px0 = blockIdx.x * 64;
    const int y   = px0 >> 9;
    const int x0  = px0 & 511;

    ((float*)(smem + SM_BIAS))[t] = bias[t];
    ((float*)(smem + SM_WM))[t]   = wm[t];

    float acc[4][4][4];
#pragma unroll
    for (int i = 0; i < 4; i++)
#pragma unroll
        for (int j = 0; j < 4; j++)
#pragma unroll
            for (int k = 0; k < 4; k++) acc[i][j][k] = 0.0f;

    // ---- A slab cp.async: 24 rows (g*3+ry) x 38 16B-chunks (2 px each) = 912 ----
    auto a_issue = [&](int icc, int stg) {
        const uint32_t base = sb + (uint32_t)(SM_A + stg * ASTAGE);
#pragma unroll
        for (int c = 0; c < 4; c++) {
            const int idx = t + c * 256;
            if (idx < 912) {
                const int r  = idx / 38;          // g*3 + ry
                const int ch = idx % 38;
                const int g  = r / 3;
                const int gy = y + (r % 3) - 1;
                const int gx0 = x0 - 4 + ch * 2;
                const bool ok = (gy >= 0) && (gy < HH) && (gx0 >= 0) && (gx0 < WW);
                const uint32_t dst = base + (uint32_t)(r * (PADXQ * 8) + ch * 16);
                const uint2* src = inp + ((size_t)(icc * 8 + g) * NPIX
                                   + (size_t)(ok ? gy : 0) * WW + (ok ? gx0 : 0));
                cp16z(dst, src, ok ? 16u : 0u);
            }
        }
        CP_COMMIT();
    };

    // B base (uint2 units): [half][q][kstep][ntile][lane]
    const uint32_t b_nwoff = (uint32_t)(w >> 2) * (72u * 1024u)
                           + (uint32_t)(w & 3) * 128u + (uint32_t)lane;
    const uint2* wb2 = (const uint2*)g_Wb;

    const int frag_p = lane & 3;
    const int frag_m = lane >> 2;

    a_issue(0, 0);
    CP_WAIT0();
    __syncthreads();

#pragma unroll 1
    for (int icc = 0; icc < 8; icc++) {
        const int stg = icc & 1;
        if (icc < 7) a_issue(icc + 1, stg ^ 1);
        const uint32_t abase = sb + (uint32_t)(SM_A + stg * ASTAGE);

#pragma unroll 1
        for (int tap = 0; tap < 9; tap++) {
            const int ky = tap / 3, kx = tap % 3;
            const uint32_t bq = (uint32_t)(icc * 9 + tap) * 1024u + b_nwoff;

            uint2 bf[2][4];
#pragma unroll
            for (int ks = 0; ks < 2; ks++)
#pragma unroll
                for (int j = 0; j < 4; j++)
                    bf[ks][j] = __ldg(wb2 + bq + (uint32_t)ks * 512u + (uint32_t)j * 32u);

#pragma unroll
            for (int ks = 0; ks < 2; ks++) {
                const int g = ks * 4 + frag_p;
                const uint32_t a0 = abase
                    + (uint32_t)((g * 3 + ky) * PADXQ + kx + 3 + frag_m) * 8u;
#pragma unroll
                for (int mt = 0; mt < 4; mt++) {
                    const uint32_t am = a0 + (uint32_t)(mt * 16) * 8u;
                    const uint2 lo = lds64(am);        // (m,   pair p) , (m,   pair p+4)
                    const uint2 hi = lds64(am + 64u);  // (m+8, pair p) , (m+8, pair p+4)
                    uint32_t af[4] = { lo.x, hi.x, lo.y, hi.y };
#pragma unroll
                    for (int j = 0; j < 4; j++) {
                        uint32_t bb[2] = { bf[ks][j].x, bf[ks][j].y };
                        mma_bf16(acc[mt][j], af, bb);
                    }
                }
            }
        }
        CP_WAIT0();          // next slab landed (issued 9 taps ago)
        __syncthreads();     // all readers of current slab done before reuse
    }

    // ---- epilogue ----
    const float* sBias = (const float*)(smem + SM_BIAS);
    const float* sWm   = (const float*)(smem + SM_WM);
    float* sRed        = (float*)(smem + SM_RED);
    float* sMask       = (float*)(smem + SM_MASK);

    float lp[4][2];
#pragma unroll
    for (int mt = 0; mt < 4; mt++) { lp[mt][0] = 0.f; lp[mt][1] = 0.f; }

#pragma unroll
    for (int mt = 0; mt < 4; mt++) {
#pragma unroll
        for (int j = 0; j < 4; j++) {
            const int ocl = w * 32 + j * 8 + 2 * (lane & 3);
            const float b0 = sBias[ocl], b1 = sBias[ocl + 1];
            const float w0 = sWm[ocl],   w1 = sWm[ocl + 1];
            float v00 = fmaxf(acc[mt][j][0] + b0, 0.f);
            float v01 = fmaxf(acc[mt][j][1] + b1, 0.f);
            float v10 = fmaxf(acc[mt][j][2] + b0, 0.f);
            float v11 = fmaxf(acc[mt][j][3] + b1, 0.f);
            lp[mt][0] = fmaf(w0, v00, fmaf(w1, v01, lp[mt][0]));
            lp[mt][1] = fmaf(w0, v10, fmaf(w1, v11, lp[mt][1]));
        }
    }
#pragma unroll
    for (int mt = 0; mt < 4; mt++)
#pragma unroll
        for (int r = 0; r < 2; r++) {
            float v = lp[mt][r];
            v += __shfl_xor_sync(0xffffffffu, v, 1);
            v += __shfl_xor_sync(0xffffffffu, v, 2);
            lp[mt][r] = v;
        }
    if ((lane & 3) == 0) {
#pragma unroll
        for (int mt = 0; mt < 4; mt++) {
            const int pxl = mt * 16 + (lane >> 2);
            sRed[w * 64 + pxl]     = lp[mt][0];
            sRed[w * 64 + pxl + 8] = lp[mt][1];
        }
    }
    __syncthreads();
    if (t < 64) {
        float s = 0.f;
#pragma unroll
        for (int z = 0; z < 8; z++) s += sRed[z * 64 + t];
        if (mres) {
            float lgt = bmp[0] + logitM[px0 + t] + s;
            sMask[t] = 1.0f / (1.0f + expf(-lgt));
        } else {
            logit[px0 + t] = s;
        }
    }

    if (mres) {
        __syncthreads();   // sMask visible to all warps
#pragma unroll
        for (int mt = 0; mt < 4; mt++) {
            const int pxl = mt * 16 + (lane >> 2);
            const int pxa = px0 + pxl;
            const int pxb = pxa + 8;
            const float ma = sMask[pxl];
            const float mb = sMask[pxl + 8];
#pragma unroll
            for (int j = 0; j < 4; j++) {
                const int ocl = w * 32 + j * 8 + 2 * (lane & 3);
                const float b0 = sBias[ocl], b1 = sBias[ocl + 1];
                float v00 = fmaxf(acc[mt][j][0] + b0, 0.f);
                float v01 = fmaxf(acc[mt][j][1] + b1, 0.f);
                float v10 = fmaxf(acc[mt][j][2] + b0, 0.f);
                float v11 = fmaxf(acc[mt][j][3] + b1, 0.f);
                const size_t i00 = (size_t)ocl       * NPIX + pxa;
                const size_t i01 = (size_t)(ocl + 1) * NPIX + pxa;
                const size_t i10 = (size_t)ocl       * NPIX + pxb;
                const size_t i11 = (size_t)(ocl + 1) * NPIX + pxb;
                outp[i00] = fmaf(ma, v00, __ldg(mres + i00));
                outp[i01] = fmaf(ma, v01, __ldg(mres + i01));
                outp[i10] = fmaf(mb, v10, __ldg(mres + i10));
                outp[i11] = fmaf(mb, v11, __ldg(mres + i11));
            }
        }
    }
}

// ---------------------------------------------------------------------------
// launch: fork-join overlap (R13) + new layouts
// ---------------------------------------------------------------------------
extern "C" void kernel_launch(void* const* d_in, const int* in_sizes, int n_in,
                              void* d_out, int out_size) {
    const float* m  = (const float*)d_in[0];
    const float* fb = (const float*)d_in[1];
    const float* fu = (const float*)d_in[2];
    const float* fd = (const float*)d_in[3];
    const float* Wf = (const float*)d_in[4];
    const float* bf = (const float*)d_in[5];
    const float* Wm = (const float*)d_in[6];
    const float* bm = (const float*)d_in[7];
    float* out = (float*)d_out;

    uint2* gMp   = nullptr; cudaGetSymbolAddress((void**)&gMp,   g_mp);
    uint2* gAuxp = nullptr; cudaGetSymbolAddress((void**)&gAuxp, g_auxp);
    float* gLM   = nullptr; cudaGetSymbolAddress((void**)&gLM,   g_logitM);

    static cudaStream_t s1 = nullptr;
    static cudaEvent_t evFork = nullptr, evJoin = nullptr;
    if (!s1) {
        cudaStreamCreateWithFlags(&s1, cudaStreamNonBlocking);
        cudaEventCreateWithFlags(&evFork, cudaEventDisableTiming);
        cudaEventCreateWithFlags(&evJoin, cudaEventDisableTiming);
        cudaFuncSetAttribute(conv_mma, cudaFuncAttributeMaxDynamicSharedMemorySize, SMEM_SZ);
    }

    cudaEventRecord(evFork, 0);
    cudaStreamWaitEvent(s1, evFork, 0);

    // side stream: geometry + aux construction
    geo_kernel<<<(NPIX + 255) / 256, 256, 0, s1>>>();
    aux_kernel<<<(32 * NPIX + 255) / 256, 256, 0, s1>>>(fb, fd, fu);
    cudaEventRecord(evJoin, s1);

    // main stream: weights + pack + main conv
    wtb_kernel<<<(2 * 72 * 2 * 16 * 32 + 255) / 256, 256>>>(Wf);
    packm_kernel<<<(32 * NPIX + 255) / 256, 256>>>(m);
    conv_mma<<<NPIX / 64, 256, SMEM_SZ>>>(gMp, bf, Wm, nullptr, gLM,
                                          nullptr, nullptr, nullptr);

    // join, then fused aux conv -> final output
    cudaStreamWaitEvent(0, evJoin, 0);
    conv_mma<<<NPIX / 64, 256, SMEM_SZ>>>(gAuxp, bf, Wm + CC, out, nullptr,
                                          m, gLM, bm);
}

// round 15
// speedup vs baseline: 1.1089x; 1.1089x over previous
#include <cuda_runtime.h>
#include <stdint.h>
#include <math.h>

#define CC    256
#define HH    256
#define WW    512
#define NPIX  (HH*WW)      // 131072
#define FH    256

// ---------------------------------------------------------------------------
// Device scratch (static — no allocations allowed)
// ---------------------------------------------------------------------------
__device__ uint32_t g_mp  [(size_t)128 * NPIX];   // m packed bf16x2 (64MB)
__device__ uint32_t g_auxp[(size_t)128 * NPIX];   // aux packed bf16x2 (64MB)
__device__ uint32_t g_Wb  [2 * 72 * 2 * 16 * 32 * 2];  // bf16x2 frag-ordered (1.18MB)
__device__ float    g_logitM[NPIX];
__device__ int      g_face [NPIX];
__device__ int      g_off  [NPIX * 4];
__device__ float    g_gw   [NPIX * 4];

// ---------------------------------------------------------------------------
// helpers
// ---------------------------------------------------------------------------
__device__ __forceinline__ uint32_t smem_u32(const void* p) {
    uint32_t a;
    asm("{ .reg .u64 t; cvta.to.shared.u64 t, %1; cvt.u32.u64 %0, t; }" : "=r"(a) : "l"(p));
    return a;
}
__device__ __forceinline__ uint32_t pack_bf16x2(float hi, float lo) {
    uint32_t u;
    asm("cvt.rn.bf16x2.f32 %0, %1, %2;" : "=r"(u) : "f"(hi), "f"(lo));
    return u;
}
__device__ __forceinline__ uint32_t lds32(uint32_t a) {
    uint32_t r; asm volatile("ld.shared.b32 %0, [%1];" : "=r"(r) : "r"(a)); return r;
}
__device__ __forceinline__ void cp16z(uint32_t sdst, const void* gsrc, uint32_t sz) {
    asm volatile("cp.async.cg.shared.global [%0], [%1], 16, %2;"
                 :: "r"(sdst), "l"(gsrc), "r"(sz) : "memory");
}
#define CP_COMMIT() asm volatile("cp.async.commit_group;" ::: "memory")
#define CP_WAIT0()  asm volatile("cp.async.wait_group 0;" ::: "memory")
__device__ __forceinline__ void mma_bf16(float* d, const uint32_t* a, const uint32_t* b) {
    asm volatile(
        "mma.sync.aligned.m16n8k16.row.col.f32.bf16.bf16.f32 "
        "{%0,%1,%2,%3}, {%4,%5,%6,%7}, {%8,%9}, {%0,%1,%2,%3};"
        : "+f"(d[0]), "+f"(d[1]), "+f"(d[2]), "+f"(d[3])
        : "r"(a[0]), "r"(a[1]), "r"(a[2]), "r"(a[3]), "r"(b[0]), "r"(b[1]));
}

// ---------------------------------------------------------------------------
// 1) per-pixel cube2equi geometry
// ---------------------------------------------------------------------------
__global__ void geo_kernel() {
    int p = blockIdx.x * blockDim.x + threadIdx.x;
    if (p >= NPIX) return;
    int oy = p / WW, ox = p % WW;
    const float PI = 3.14159265358979323846f;
    float theta = ((ox + 0.5f) / (float)WW) * (2.0f * PI) - PI;
    float phi   = 0.5f * PI - ((oy + 0.5f) / (float)HH) * PI;
    float st = sinf(theta), ct = cosf(theta);
    float sp = sinf(phi),   cp = cosf(phi);
    float dx = cp * st, dy = sp, dz = cp * ct;
    float ax = fabsf(dx), ay = fabsf(dy), az = fabsf(dz);
    float mx = fmaxf(fmaxf(ax, ay), az);
    float px = dx / mx, py = dy / mx, pz = dz / mx;
    bool cz = (az >= ax) && (az >= ay);
    bool cx = (!cz) && (ax >= ay);
    int face = cz ? (dz > 0.f ? 2 : 0) : cx ? (dx > 0.f ? 4 : 3) : (dy > 0.f ? 5 : 1);
    float a  = cz ? (dz > 0.f ? px : -px) : cx ? (dx > 0.f ? -pz : pz) : px;
    float bc = (cz || cx) ? -py : (dy > 0.f ? pz : -pz);
    float uu = fminf(fmaxf((a  + 1.0f) * 0.5f * (float)(FH - 1), 0.0f), (float)(FH - 1));
    float vv = fminf(fmaxf((bc + 1.0f) * 0.5f * (float)(FH - 1), 0.0f), (float)(FH - 1));
    int u0 = (int)floorf(uu), v0 = (int)floorf(vv);
    int u1 = min(u0 + 1, FH - 1), v1 = min(v0 + 1, FH - 1);
    float wu = uu - (float)u0, wv = vv - (float)v0;
    g_face[p] = face;
    g_off[p*4+0] = v0 * FH + u0; g_off[p*4+1] = v0 * FH + u1;
    g_off[p*4+2] = v1 * FH + u0; g_off[p*4+3] = v1 * FH + u1;
    g_gw [p*4+0] = (1.f-wv)*(1.f-wu); g_gw[p*4+1] = (1.f-wv)*wu;
    g_gw [p*4+2] = wv*(1.f-wu);       g_gw[p*4+3] = wv*wu;
}

// ---------------------------------------------------------------------------
// 2a) pack m -> bf16x2 pairs: g_mp[pair][p] ; 2 pair-rows per thread for MLP
// ---------------------------------------------------------------------------
__global__ void packm_kernel(const float* __restrict__ m) {
    int idx = blockIdx.x * blockDim.x + threadIdx.x;
    if (idx >= 64 * NPIX) return;
    int p  = idx & (NPIX - 1);
    int pr = idx >> 17;                    // 0..63 ; handles pr and pr+64
    const float* m0 = m + (size_t)(2 * pr) * NPIX + p;
    float a0 = __ldg(m0);
    float a1 = __ldg(m0 + NPIX);
    const float* m1 = m + (size_t)(2 * (pr + 64)) * NPIX + p;
    float b0 = __ldg(m1);
    float b1 = __ldg(m1 + NPIX);
    g_mp[(size_t)pr * NPIX + p]        = pack_bf16x2(a1, a0);
    g_mp[(size_t)(pr + 64) * NPIX + p] = pack_bf16x2(b1, b0);
}

// ---------------------------------------------------------------------------
// 2b) aux = cube2equi(cube), packed bf16x2; 4 channel-pairs per thread
// ---------------------------------------------------------------------------
__global__ void aux_kernel(const float* __restrict__ fb, const float* __restrict__ fd,
                           const float* __restrict__ fu) {
    int idx = blockIdx.x * blockDim.x + threadIdx.x;
    if (idx >= 32 * NPIX) return;
    int p   = idx & (NPIX - 1);
    int pr0 = idx >> 17;            // 0..31
    int f = g_face[p];
    const float* base = (f == 0) ? fb : (f == 1) ? fd : (f == 5) ? fu : nullptr;
    if (!base) {
#pragma unroll
        for (int k = 0; k < 4; k++)
            g_auxp[(size_t)(pr0 + k * 32) * NPIX + p] = 0u;
        return;
    }
    const float4 gw = *(const float4*)&g_gw[p * 4];
    const int4   go = *(const int4*)&g_off[p * 4];
#pragma unroll
    for (int k = 0; k < 4; k++) {
        const int pr = pr0 + k * 32;
        const float* c0 = base + (size_t)(2 * pr)     * (FH * FH);
        const float* c1 = base + (size_t)(2 * pr + 1) * (FH * FH);
        float v0 = gw.x*c0[go.x] + gw.y*c0[go.y] + gw.z*c0[go.z] + gw.w*c0[go.w];
        float v1 = gw.x*c1[go.x] + gw.y*c1[go.y] + gw.z*c1[go.z] + gw.w*c1[go.w];
        g_auxp[(size_t)pr * NPIX + p] = pack_bf16x2(v1, v0);
    }
}

// ---------------------------------------------------------------------------
// 3) weights -> bf16x2 fragment order for m16n8k16 (layout validated in R7)
// ---------------------------------------------------------------------------
__global__ void wtb_kernel(const float* __restrict__ Wf) {
    int idx = blockIdx.x * blockDim.x + threadIdx.x;
    if (idx >= 2 * 72 * 2 * 16 * 32) return;
    int lane  = idx & 31;
    int ntile = (idx >> 5) & 15;
    int kstep = (idx >> 9) & 1;
    int qq    = idx >> 10;
    int q     = qq % 72;
    int half  = qq / 72;
    int icc = q / 9, tap = q % 9;
    int oc  = half * 128 + ntile * 8 + (lane >> 2);
    int ic  = icc * 32 + kstep * 16 + (lane & 3) * 2;
    const float* wp = Wf + (size_t)oc * CC * 9 + tap;
    float w0 = wp[(size_t)ic * 9];
    float w1 = wp[(size_t)(ic + 1) * 9];
    float w8 = wp[(size_t)(ic + 8) * 9];
    float w9 = wp[(size_t)(ic + 9) * 9];
    g_Wb[idx * 2 + 0] = pack_bf16x2(w1, w0);
    g_Wb[idx * 2 + 1] = pack_bf16x2(w9, w8);
}

// ---------------------------------------------------------------------------
// 4) bf16 mma.sync conv, 2 CTAs/SM (R12/R13 proven form, unchanged):
//    CTA = 64 px x 256 oc, 256 threads, 8 warps (1M x 8N); warp 64px x 32oc.
// ---------------------------------------------------------------------------
#define PADX    88
#define PAIRSTR (3 * PADX)               // 264 ; lane stride 792 % 32 == 24 -> conflict-free
#define ASTAGE  (16 * PAIRSTR * 4)       // 16896 bytes per stage
#define SM_A     0
#define SM_BIAS  (2 * ASTAGE)            // 33792
#define SM_WM    (SM_BIAS + 1024)
#define SM_RED   (SM_WM + 1024)
#define SM_MASK  (SM_RED + 2048)
#define SMEM_SZ  (SM_MASK + 256)         // 38112

__global__ __launch_bounds__(256, 2)
void conv_mma(const uint32_t* __restrict__ inp,   // packed bf16x2 [128][NPIX]
              const float* __restrict__ bias,
              const float* __restrict__ wm, float* __restrict__ outp,
              float* __restrict__ logit,
              const float* __restrict__ mres,     // non-null => fused final mode
              const float* __restrict__ logitM,
              const float* __restrict__ bmp)
{
    extern __shared__ char smem[];
    const uint32_t sb = smem_u32(smem);

    const int t    = threadIdx.x;
    const int w    = t >> 5;        // 0..7 : oc eighth (32 oc)
    const int lane = t & 31;

    const int px0 = blockIdx.x * 64;
    const int y   = px0 >> 9;
    const int x0  = px0 & 511;

    ((float*)(smem + SM_BIAS))[t] = bias[t];
    ((float*)(smem + SM_WM))[t]   = wm[t];

    float acc[4][4][4];
#pragma unroll
    for (int i = 0; i < 4; i++)
#pragma unroll
        for (int j = 0; j < 4; j++)
#pragma unroll
            for (int k = 0; k < 4; k++) acc[i][j][k] = 0.0f;

    // ---- A slab cp.async: 48 rows x 18 16B-chunks = 864 ; col 0 <-> gx0-4 ----
    auto a_issue = [&](int icc, int stg) {
        const uint32_t base = sb + (uint32_t)(SM_A + stg * ASTAGE);
#pragma unroll
        for (int c = 0; c < 4; c++) {
            const int idx = t + c * 256;
            if (idx < 864) {
                const int r  = idx / 18;
                const int cc = idx % 18;
                const int pr = icc * 16 + r / 3;
                const int gy = y + (r % 3) - 1;
                const int gx0 = x0 - 4 + cc * 4;
                const bool ok = (gy >= 0) && (gy < HH) && (gx0 >= 0) && (gx0 + 3 < WW);
                const uint32_t dst = base + (uint32_t)((r * PADX + cc * 4) * 4);
                const uint32_t* src = inp + ((size_t)pr * NPIX
                                     + (size_t)(ok ? gy : 0) * WW + (ok ? gx0 : 0));
                cp16z(dst, src, ok ? 16u : 0u);
            }
        }
        CP_COMMIT();
    };

    // B base (uint2 units): [half][q][kstep][ntile][lane]
    const uint32_t b_nwoff = (uint32_t)(w >> 2) * (72u * 1024u)
                           + (uint32_t)(w & 3) * 128u + (uint32_t)lane;
    const uint2* wb2 = (const uint2*)g_Wb;

    const int frag_p = lane & 3;
    const int frag_m = lane >> 2;

    a_issue(0, 0);
    CP_WAIT0();
    __syncthreads();

#pragma unroll 1
    for (int icc = 0; icc < 8; icc++) {
        const int stg = icc & 1;
        if (icc < 7) a_issue(icc + 1, stg ^ 1);
        const uint32_t abase = sb + (uint32_t)(SM_A + stg * ASTAGE);

#pragma unroll 1
        for (int tap = 0; tap < 9; tap++) {
            const int ky = tap / 3, kx = tap % 3;
            const uint32_t bq = (uint32_t)(icc * 9 + tap) * 1024u + b_nwoff;

            uint2 bf[2][4];
#pragma unroll
            for (int ks = 0; ks < 2; ks++)
#pragma unroll
                for (int j = 0; j < 4; j++)
                    bf[ks][j] = __ldg(wb2 + bq + (uint32_t)ks * 512u + (uint32_t)j * 32u);

#pragma unroll
            for (int ks = 0; ks < 2; ks++) {
                const int p0 = ks * 8 + frag_p;
                const uint32_t a0 = abase
                    + (uint32_t)((p0 * 3 + ky) * PADX + kx + 3 + frag_m) * 4u;
#pragma unroll
                for (int mt = 0; mt < 4; mt++) {
                    uint32_t af[4];
                    const uint32_t am = a0 + (uint32_t)(mt * 16) * 4u;
                    af[0] = lds32(am);
                    af[1] = lds32(am + 32u);
                    af[2] = lds32(am + 4u * PAIRSTR * 4u);
                    af[3] = lds32(am + 4u * PAIRSTR * 4u + 32u);
#pragma unroll
                    for (int j = 0; j < 4; j++) {
                        uint32_t bb[2] = { bf[ks][j].x, bf[ks][j].y };
                        mma_bf16(acc[mt][j], af, bb);
                    }
                }
            }
        }
        CP_WAIT0();          // next slab landed (issued 9 taps ago)
        __syncthreads();     // all readers of current slab done before reuse
    }

    // ---- epilogue ----
    const float* sBias = (const float*)(smem + SM_BIAS);
    const float* sWm   = (const float*)(smem + SM_WM);
    float* sRed        = (float*)(smem + SM_RED);
    float* sMask       = (float*)(smem + SM_MASK);

    float lp[4][2];
#pragma unroll
    for (int mt = 0; mt < 4; mt++) { lp[mt][0] = 0.f; lp[mt][1] = 0.f; }

#pragma unroll
    for (int mt = 0; mt < 4; mt++) {
#pragma unroll
        for (int j = 0; j < 4; j++) {
            const int ocl = w * 32 + j * 8 + 2 * (lane & 3);
            const float b0 = sBias[ocl], b1 = sBias[ocl + 1];
            const float w0 = sWm[ocl],   w1 = sWm[ocl + 1];
            float v00 = fmaxf(acc[mt][j][0] + b0, 0.f);
            float v01 = fmaxf(acc[mt][j][1] + b1, 0.f);
            float v10 = fmaxf(acc[mt][j][2] + b0, 0.f);
            float v11 = fmaxf(acc[mt][j][3] + b1, 0.f);
            lp[mt][0] = fmaf(w0, v00, fmaf(w1, v01, lp[mt][0]));
            lp[mt][1] = fmaf(w0, v10, fmaf(w1, v11, lp[mt][1]));
        }
    }
#pragma unroll
    for (int mt = 0; mt < 4; mt++)
#pragma unroll
        for (int r = 0; r < 2; r++) {
            float v = lp[mt][r];
            v += __shfl_xor_sync(0xffffffffu, v, 1);
            v += __shfl_xor_sync(0xffffffffu, v, 2);
            lp[mt][r] = v;
        }
    if ((lane & 3) == 0) {
#pragma unroll
        for (int mt = 0; mt < 4; mt++) {
            const int pxl = mt * 16 + (lane >> 2);
            sRed[w * 64 + pxl]     = lp[mt][0];
            sRed[w * 64 + pxl + 8] = lp[mt][1];
        }
    }
    __syncthreads();
    if (t < 64) {
        float s = 0.f;
#pragma unroll
        for (int z = 0; z < 8; z++) s += sRed[z * 64 + t];
        if (mres) {
            float lgt = bmp[0] + logitM[px0 + t] + s;
            sMask[t] = 1.0f / (1.0f + expf(-lgt));
        } else {
            logit[px0 + t] = s;
        }
    }

    if (mres) {
        __syncthreads();   // sMask visible to all warps
#pragma unroll
        for (int mt = 0; mt < 4; mt++) {
            const int pxl = mt * 16 + (lane >> 2);
            const int pxa = px0 + pxl;
            const int pxb = pxa + 8;
            const float ma = sMask[pxl];
            const float mb = sMask[pxl + 8];
#pragma unroll
            for (int j = 0; j < 4; j++) {
                const int ocl = w * 32 + j * 8 + 2 * (lane & 3);
                const float b0 = sBias[ocl], b1 = sBias[ocl + 1];
                float v00 = fmaxf(acc[mt][j][0] + b0, 0.f);
                float v01 = fmaxf(acc[mt][j][1] + b1, 0.f);
                float v10 = fmaxf(acc[mt][j][2] + b0, 0.f);
                float v11 = fmaxf(acc[mt][j][3] + b1, 0.f);
                const size_t i00 = (size_t)ocl       * NPIX + pxa;
                const size_t i01 = (size_t)(ocl + 1) * NPIX + pxa;
                const size_t i10 = (size_t)ocl       * NPIX + pxb;
                const size_t i11 = (size_t)(ocl + 1) * NPIX + pxb;
                outp[i00] = fmaf(ma, v00, __ldg(mres + i00));
                outp[i01] = fmaf(ma, v01, __ldg(mres + i01));
                outp[i10] = fmaf(mb, v10, __ldg(mres + i10));
                outp[i11] = fmaf(mb, v11, __ldg(mres + i11));
            }
        }
    }
}

// ---------------------------------------------------------------------------
// launch: fork-join overlap — side stream: wtb -> geo -> aux ;
// main stream: packm -> conv_main ; conv_aux joins both.
// (wtb completes long before conv_main needs g_Wb; join event enforces it.)
// ---------------------------------------------------------------------------
extern "C" void kernel_launch(void* const* d_in, const int* in_sizes, int n_in,
                              void* d_out, int out_size) {
    const float* m  = (const float*)d_in[0];
    const float* fb = (const float*)d_in[1];
    const float* fu = (const float*)d_in[2];
    const float* fd = (const float*)d_in[3];
    const float* Wf = (const float*)d_in[4];
    const float* bf = (const float*)d_in[5];
    const float* Wm = (const float*)d_in[6];
    const float* bm = (const float*)d_in[7];
    float* out = (float*)d_out;

    uint32_t* gMp   = nullptr; cudaGetSymbolAddress((void**)&gMp,   g_mp);
    uint32_t* gAuxp = nullptr; cudaGetSymbolAddress((void**)&gAuxp, g_auxp);
    float*    gLM   = nullptr; cudaGetSymbolAddress((void**)&gLM,   g_logitM);

    static cudaStream_t s1 = nullptr;
    static cudaEvent_t evFork = nullptr, evJoin = nullptr, evWtb = nullptr;
    if (!s1) {
        cudaStreamCreateWithFlags(&s1, cudaStreamNonBlocking);
        cudaEventCreateWithFlags(&evFork, cudaEventDisableTiming);
        cudaEventCreateWithFlags(&evJoin, cudaEventDisableTiming);
        cudaEventCreateWithFlags(&evWtb,  cudaEventDisableTiming);
        cudaFuncSetAttribute(conv_mma, cudaFuncAttributeMaxDynamicSharedMemorySize, SMEM_SZ);
    }

    // fork side stream off the main (capture) stream
    cudaEventRecord(evFork, 0);
    cudaStreamWaitEvent(s1, evFork, 0);

    // side stream: weights, geometry, aux construction
    wtb_kernel<<<(2 * 72 * 2 * 16 * 32 + 255) / 256, 256, 0, s1>>>(Wf);
    cudaEventRecord(evWtb, s1);
    geo_kernel<<<(NPIX + 255) / 256, 256, 0, s1>>>();
    aux_kernel<<<(32 * NPIX + 255) / 256, 256, 0, s1>>>(fb, fd, fu);
    cudaEventRecord(evJoin, s1);

    // main stream: pack m, wait for weights, main conv
    packm_kernel<<<(64 * NPIX + 255) / 256, 256>>>(m);
    cudaStreamWaitEvent(0, evWtb, 0);
    conv_mma<<<NPIX / 64, 256, SMEM_SZ>>>(gMp, bf, Wm, nullptr, gLM,
                                          nullptr, nullptr, nullptr);

    // join, then fused aux conv -> final output
    cudaStreamWaitEvent(0, evJoin, 0);
    conv_mma<<<NPIX / 64, 256, SMEM_SZ>>>(gAuxp, bf, Wm + CC, out, nullptr,
                                          m, gLM, bm);
}

// round 16
// speedup vs baseline: 1.1606x; 1.0466x over previous
#include <cuda_runtime.h>
#include <stdint.h>
#include <math.h>

#define CC    256
#define HH    256
#define WW    512
#define NPIX  (HH*WW)      // 131072
#define FH    256

// ---------------------------------------------------------------------------
// Device scratch (static — no allocations allowed)
// ---------------------------------------------------------------------------
__device__ uint32_t g_mp  [(size_t)128 * NPIX];   // m packed bf16x2 (64MB)
__device__ uint32_t g_auxp[(size_t)128 * NPIX];   // aux packed bf16x2 (64MB)
__device__ uint32_t g_Wb  [2 * 72 * 2 * 16 * 32 * 2];  // bf16x2 frag-ordered (1.18MB)
__device__ float    g_logitM[NPIX];
__device__ int      g_face [NPIX];
__device__ int      g_off  [NPIX * 4];
__device__ float    g_gw   [NPIX * 4];

// ---------------------------------------------------------------------------
// helpers
// ---------------------------------------------------------------------------
__device__ __forceinline__ uint32_t smem_u32(const void* p) {
    uint32_t a;
    asm("{ .reg .u64 t; cvta.to.shared.u64 t, %1; cvt.u32.u64 %0, t; }" : "=r"(a) : "l"(p));
    return a;
}
__device__ __forceinline__ uint32_t pack_bf16x2(float hi, float lo) {
    uint32_t u;
    asm("cvt.rn.bf16x2.f32 %0, %1, %2;" : "=r"(u) : "f"(hi), "f"(lo));
    return u;
}
__device__ __forceinline__ uint32_t lds32(uint32_t a) {
    uint32_t r; asm volatile("ld.shared.b32 %0, [%1];" : "=r"(r) : "r"(a)); return r;
}
__device__ __forceinline__ void cp16z(uint32_t sdst, const void* gsrc, uint32_t sz) {
    asm volatile("cp.async.cg.shared.global [%0], [%1], 16, %2;"
                 :: "r"(sdst), "l"(gsrc), "r"(sz) : "memory");
}
#define CP_COMMIT() asm volatile("cp.async.commit_group;" ::: "memory")
#define CP_WAIT0()  asm volatile("cp.async.wait_group 0;" ::: "memory")
__device__ __forceinline__ void mma_bf16(float* d, const uint32_t* a, const uint32_t* b) {
    asm volatile(
        "mma.sync.aligned.m16n8k16.row.col.f32.bf16.bf16.f32 "
        "{%0,%1,%2,%3}, {%4,%5,%6,%7}, {%8,%9}, {%0,%1,%2,%3};"
        : "+f"(d[0]), "+f"(d[1]), "+f"(d[2]), "+f"(d[3])
        : "r"(a[0]), "r"(a[1]), "r"(a[2]), "r"(a[3]), "r"(b[0]), "r"(b[1]));
}

// ---------------------------------------------------------------------------
// 1) per-pixel cube2equi geometry
// ---------------------------------------------------------------------------
__global__ void geo_kernel() {
    int p = blockIdx.x * blockDim.x + threadIdx.x;
    if (p >= NPIX) return;
    int oy = p / WW, ox = p % WW;
    const float PI = 3.14159265358979323846f;
    float theta = ((ox + 0.5f) / (float)WW) * (2.0f * PI) - PI;
    float phi   = 0.5f * PI - ((oy + 0.5f) / (float)HH) * PI;
    float st = sinf(theta), ct = cosf(theta);
    float sp = sinf(phi),   cp = cosf(phi);
    float dx = cp * st, dy = sp, dz = cp * ct;
    float ax = fabsf(dx), ay = fabsf(dy), az = fabsf(dz);
    float mx = fmaxf(fmaxf(ax, ay), az);
    float px = dx / mx, py = dy / mx, pz = dz / mx;
    bool cz = (az >= ax) && (az >= ay);
    bool cx = (!cz) && (ax >= ay);
    int face = cz ? (dz > 0.f ? 2 : 0) : cx ? (dx > 0.f ? 4 : 3) : (dy > 0.f ? 5 : 1);
    float a  = cz ? (dz > 0.f ? px : -px) : cx ? (dx > 0.f ? -pz : pz) : px;
    float bc = (cz || cx) ? -py : (dy > 0.f ? pz : -pz);
    float uu = fminf(fmaxf((a  + 1.0f) * 0.5f * (float)(FH - 1), 0.0f), (float)(FH - 1));
    float vv = fminf(fmaxf((bc + 1.0f) * 0.5f * (float)(FH - 1), 0.0f), (float)(FH - 1));
    int u0 = (int)floorf(uu), v0 = (int)floorf(vv);
    int u1 = min(u0 + 1, FH - 1), v1 = min(v0 + 1, FH - 1);
    float wu = uu - (float)u0, wv = vv - (float)v0;
    g_face[p] = face;
    g_off[p*4+0] = v0 * FH + u0; g_off[p*4+1] = v0 * FH + u1;
    g_off[p*4+2] = v1 * FH + u0; g_off[p*4+3] = v1 * FH + u1;
    g_gw [p*4+0] = (1.f-wv)*(1.f-wu); g_gw[p*4+1] = (1.f-wv)*wu;
    g_gw [p*4+2] = wv*(1.f-wu);       g_gw[p*4+3] = wv*wu;
}

// ---------------------------------------------------------------------------
// 2a) pack m -> bf16x2 pairs: 2 pixels x 2 pair-rows per thread (MLP=4, wide)
// ---------------------------------------------------------------------------
__global__ void packm_kernel(const float* __restrict__ m) {
    int idx = blockIdx.x * blockDim.x + threadIdx.x;
    if (idx >= 32 * NPIX) return;
    int p2 = idx & (NPIX / 2 - 1);         // pixel pair index
    int pr = idx >> 16;                    // 0..63 ; handles pr and pr+64
    int p  = p2 * 2;
    const float2* r0a = (const float2*)(m + (size_t)(2 * pr) * NPIX + p);
    const float2* r0b = (const float2*)(m + (size_t)(2 * pr + 1) * NPIX + p);
    const float2* r1a = (const float2*)(m + (size_t)(2 * (pr + 64)) * NPIX + p);
    const float2* r1b = (const float2*)(m + (size_t)(2 * (pr + 64) + 1) * NPIX + p);
    float2 a0 = __ldg(r0a), a1 = __ldg(r0b);
    float2 b0 = __ldg(r1a), b1 = __ldg(r1b);
    uint2 va, vb;
    va.x = pack_bf16x2(a1.x, a0.x); va.y = pack_bf16x2(a1.y, a0.y);
    vb.x = pack_bf16x2(b1.x, b0.x); vb.y = pack_bf16x2(b1.y, b0.y);
    *(uint2*)(g_mp + (size_t)pr * NPIX + p)        = va;
    *(uint2*)(g_mp + (size_t)(pr + 64) * NPIX + p) = vb;
}

// ---------------------------------------------------------------------------
// 2b) aux = cube2equi(cube), packed bf16x2; 4 channel-pairs per thread
// ---------------------------------------------------------------------------
__global__ void aux_kernel(const float* __restrict__ fb, const float* __restrict__ fd,
                           const float* __restrict__ fu) {
    int idx = blockIdx.x * blockDim.x + threadIdx.x;
    if (idx >= 32 * NPIX) return;
    int p   = idx & (NPIX - 1);
    int pr0 = idx >> 17;            // 0..31
    int f = g_face[p];
    const float* base = (f == 0) ? fb : (f == 1) ? fd : (f == 5) ? fu : nullptr;
    if (!base) {
#pragma unroll
        for (int k = 0; k < 4; k++)
            g_auxp[(size_t)(pr0 + k * 32) * NPIX + p] = 0u;
        return;
    }
    const float4 gw = *(const float4*)&g_gw[p * 4];
    const int4   go = *(const int4*)&g_off[p * 4];
#pragma unroll
    for (int k = 0; k < 4; k++) {
        const int pr = pr0 + k * 32;
        const float* c0 = base + (size_t)(2 * pr)     * (FH * FH);
        const float* c1 = base + (size_t)(2 * pr + 1) * (FH * FH);
        float v0 = gw.x*c0[go.x] + gw.y*c0[go.y] + gw.z*c0[go.z] + gw.w*c0[go.w];
        float v1 = gw.x*c1[go.x] + gw.y*c1[go.y] + gw.z*c1[go.z] + gw.w*c1[go.w];
        g_auxp[(size_t)pr * NPIX + p] = pack_bf16x2(v1, v0);
    }
}

// ---------------------------------------------------------------------------
// 3) weights -> bf16x2 fragment order for m16n8k16 (layout validated in R7)
// ---------------------------------------------------------------------------
__global__ void wtb_kernel(const float* __restrict__ Wf) {
    int idx = blockIdx.x * blockDim.x + threadIdx.x;
    if (idx >= 2 * 72 * 2 * 16 * 32) return;
    int lane  = idx & 31;
    int ntile = (idx >> 5) & 15;
    int kstep = (idx >> 9) & 1;
    int qq    = idx >> 10;
    int q     = qq % 72;
    int half  = qq / 72;
    int icc = q / 9, tap = q % 9;
    int oc  = half * 128 + ntile * 8 + (lane >> 2);
    int ic  = icc * 32 + kstep * 16 + (lane & 3) * 2;
    const float* wp = Wf + (size_t)oc * CC * 9 + tap;
    float w0 = wp[(size_t)ic * 9];
    float w1 = wp[(size_t)(ic + 1) * 9];
    float w8 = wp[(size_t)(ic + 8) * 9];
    float w9 = wp[(size_t)(ic + 9) * 9];
    g_Wb[idx * 2 + 0] = pack_bf16x2(w1, w0);
    g_Wb[idx * 2 + 1] = pack_bf16x2(w9, w8);
}

// ---------------------------------------------------------------------------
// 4) bf16 mma.sync conv, 2 CTAs/SM (R12/R13 form; tap loop unrolled x3):
//    CTA = 64 px x 256 oc, 256 threads, 8 warps (1M x 8N); warp 64px x 32oc.
// ---------------------------------------------------------------------------
#define PADX    88
#define PAIRSTR (3 * PADX)               // 264 ; lane stride 792 % 32 == 24 -> conflict-free
#define ASTAGE  (16 * PAIRSTR * 4)       // 16896 bytes per stage
#define SM_A     0
#define SM_BIAS  (2 * ASTAGE)            // 33792
#define SM_WM    (SM_BIAS + 1024)
#define SM_RED   (SM_WM + 1024)
#define SM_MASK  (SM_RED + 2048)
#define SMEM_SZ  (SM_MASK + 256)         // 38112

__global__ __launch_bounds__(256, 2)
void conv_mma(const uint32_t* __restrict__ inp,   // packed bf16x2 [128][NPIX]
              const float* __restrict__ bias,
              const float* __restrict__ wm, float* __restrict__ outp,
              float* __restrict__ logit,
              const float* __restrict__ mres,     // non-null => fused final mode
              const float* __restrict__ logitM,
              const float* __restrict__ bmp)
{
    extern __shared__ char smem[];
    const uint32_t sb = smem_u32(smem);

    const int t    = threadIdx.x;
    const int w    = t >> 5;        // 0..7 : oc eighth (32 oc)
    const int lane = t & 31;

    const int px0 = blockIdx.x * 64;
    const int y   = px0 >> 9;
    const int x0  = px0 & 511;

    ((float*)(smem + SM_BIAS))[t] = bias[t];
    ((float*)(smem + SM_WM))[t]   = wm[t];

    float acc[4][4][4];
#pragma unroll
    for (int i = 0; i < 4; i++)
#pragma unroll
        for (int j = 0; j < 4; j++)
#pragma unroll
            for (int k = 0; k < 4; k++) acc[i][j][k] = 0.0f;

    // ---- A slab cp.async: 48 rows x 18 16B-chunks = 864 ; col 0 <-> gx0-4 ----
    auto a_issue = [&](int icc, int stg) {
        const uint32_t base = sb + (uint32_t)(SM_A + stg * ASTAGE);
#pragma unroll
        for (int c = 0; c < 4; c++) {
            const int idx = t + c * 256;
            if (idx < 864) {
                const int r  = idx / 18;
                const int cc = idx % 18;
                const int pr = icc * 16 + r / 3;
                const int gy = y + (r % 3) - 1;
                const int gx0 = x0 - 4 + cc * 4;
                const bool ok = (gy >= 0) && (gy < HH) && (gx0 >= 0) && (gx0 + 3 < WW);
                const uint32_t dst = base + (uint32_t)((r * PADX + cc * 4) * 4);
                const uint32_t* src = inp + ((size_t)pr * NPIX
                                     + (size_t)(ok ? gy : 0) * WW + (ok ? gx0 : 0));
                cp16z(dst, src, ok ? 16u : 0u);
            }
        }
        CP_COMMIT();
    };

    // B base (uint2 units): [half][q][kstep][ntile][lane]
    const uint32_t b_nwoff = (uint32_t)(w >> 2) * (72u * 1024u)
                           + (uint32_t)(w & 3) * 128u + (uint32_t)lane;
    const uint2* wb2 = (const uint2*)g_Wb;

    const int frag_p = lane & 3;
    const int frag_m = lane >> 2;

    a_issue(0, 0);
    CP_WAIT0();
    __syncthreads();

#pragma unroll 1
    for (int icc = 0; icc < 8; icc++) {
        const int stg = icc & 1;
        if (icc < 7) a_issue(icc + 1, stg ^ 1);
        const uint32_t abase = sb + (uint32_t)(SM_A + stg * ASTAGE);

#pragma unroll 1
        for (int ky = 0; ky < 3; ky++) {
#pragma unroll
            for (int kx = 0; kx < 3; kx++) {
                const int tap = ky * 3 + kx;
                const uint32_t bq = (uint32_t)(icc * 9 + tap) * 1024u + b_nwoff;

                uint2 bf[2][4];
#pragma unroll
                for (int ks = 0; ks < 2; ks++)
#pragma unroll
                    for (int j = 0; j < 4; j++)
                        bf[ks][j] = __ldg(wb2 + bq + (uint32_t)ks * 512u + (uint32_t)j * 32u);

#pragma unroll
                for (int ks = 0; ks < 2; ks++) {
                    const int p0 = ks * 8 + frag_p;
                    const uint32_t a0 = abase
                        + (uint32_t)((p0 * 3 + ky) * PADX + kx + 3 + frag_m) * 4u;
#pragma unroll
                    for (int mt = 0; mt < 4; mt++) {
                        uint32_t af[4];
                        const uint32_t am = a0 + (uint32_t)(mt * 16) * 4u;
                        af[0] = lds32(am);
                        af[1] = lds32(am + 32u);
                        af[2] = lds32(am + 4u * PAIRSTR * 4u);
                        af[3] = lds32(am + 4u * PAIRSTR * 4u + 32u);
#pragma unroll
                        for (int j = 0; j < 4; j++) {
                            uint32_t bb[2] = { bf[ks][j].x, bf[ks][j].y };
                            mma_bf16(acc[mt][j], af, bb);
                        }
                    }
                }
            }
        }
        CP_WAIT0();          // next slab landed (issued 9 taps ago)
        __syncthreads();     // all readers of current slab done before reuse
    }

    // ---- epilogue ----
    const float* sBias = (const float*)(smem + SM_BIAS);
    const float* sWm   = (const float*)(smem + SM_WM);
    float* sRed        = (float*)(smem + SM_RED);
    float* sMask       = (float*)(smem + SM_MASK);

    float lp[4][2];
#pragma unroll
    for (int mt = 0; mt < 4; mt++) { lp[mt][0] = 0.f; lp[mt][1] = 0.f; }

#pragma unroll
    for (int mt = 0; mt < 4; mt++) {
#pragma unroll
        for (int j = 0; j < 4; j++) {
            const int ocl = w * 32 + j * 8 + 2 * (lane & 3);
            const float b0 = sBias[ocl], b1 = sBias[ocl + 1];
            const float w0 = sWm[ocl],   w1 = sWm[ocl + 1];
            float v00 = fmaxf(acc[mt][j][0] + b0, 0.f);
            float v01 = fmaxf(acc[mt][j][1] + b1, 0.f);
            float v10 = fmaxf(acc[mt][j][2] + b0, 0.f);
            float v11 = fmaxf(acc[mt][j][3] + b1, 0.f);
            lp[mt][0] = fmaf(w0, v00, fmaf(w1, v01, lp[mt][0]));
            lp[mt][1] = fmaf(w0, v10, fmaf(w1, v11, lp[mt][1]));
        }
    }
#pragma unroll
    for (int mt = 0; mt < 4; mt++)
#pragma unroll
        for (int r = 0; r < 2; r++) {
            float v = lp[mt][r];
            v += __shfl_xor_sync(0xffffffffu, v, 1);
            v += __shfl_xor_sync(0xffffffffu, v, 2);
            lp[mt][r] = v;
        }
    if ((lane & 3) == 0) {
#pragma unroll
        for (int mt = 0; mt < 4; mt++) {
            const int pxl = mt * 16 + (lane >> 2);
            sRed[w * 64 + pxl]     = lp[mt][0];
            sRed[w * 64 + pxl + 8] = lp[mt][1];
        }
    }
    __syncthreads();
    if (t < 64) {
        float s = 0.f;
#pragma unroll
        for (int z = 0; z < 8; z++) s += sRed[z * 64 + t];
        if (mres) {
            float lgt = bmp[0] + logitM[px0 + t] + s;
            sMask[t] = 1.0f / (1.0f + expf(-lgt));
        } else {
            logit[px0 + t] = s;
        }
    }

    if (mres) {
        __syncthreads();   // sMask visible to all warps
#pragma unroll
        for (int mt = 0; mt < 4; mt++) {
            const int pxl = mt * 16 + (lane >> 2);
            const int pxa = px0 + pxl;
            const int pxb = pxa + 8;
            const float ma = sMask[pxl];
            const float mb = sMask[pxl + 8];
#pragma unroll
            for (int j = 0; j < 4; j++) {
                const int ocl = w * 32 + j * 8 + 2 * (lane & 3);
                const float b0 = sBias[ocl], b1 = sBias[ocl + 1];
                float v00 = fmaxf(acc[mt][j][0] + b0, 0.f);
                float v01 = fmaxf(acc[mt][j][1] + b1, 0.f);
                float v10 = fmaxf(acc[mt][j][2] + b0, 0.f);
                float v11 = fmaxf(acc[mt][j][3] + b1, 0.f);
                const size_t i00 = (size_t)ocl       * NPIX + pxa;
                const size_t i01 = (size_t)(ocl + 1) * NPIX + pxa;
                const size_t i10 = (size_t)ocl       * NPIX + pxb;
                const size_t i11 = (size_t)(ocl + 1) * NPIX + pxb;
                outp[i00] = fmaf(ma, v00, __ldg(mres + i00));
                outp[i01] = fmaf(ma, v01, __ldg(mres + i01));
                outp[i10] = fmaf(mb, v10, __ldg(mres + i10));
                outp[i11] = fmaf(mb, v11, __ldg(mres + i11));
            }
        }
    }
}

// ---------------------------------------------------------------------------
// launch: fork-join overlap — side stream: wtb -> geo -> aux ;
// main stream: packm -> conv_main ; conv_aux joins both.
// ---------------------------------------------------------------------------
extern "C" void kernel_launch(void* const* d_in, const int* in_sizes, int n_in,
                              void* d_out, int out_size) {
    const float* m  = (const float*)d_in[0];
    const float* fb = (const float*)d_in[1];
    const float* fu = (const float*)d_in[2];
    const float* fd = (const float*)d_in[3];
    const float* Wf = (const float*)d_in[4];
    const float* bf = (const float*)d_in[5];
    const float* Wm = (const float*)d_in[6];
    const float* bm = (const float*)d_in[7];
    float* out = (float*)d_out;

    uint32_t* gMp   = nullptr; cudaGetSymbolAddress((void**)&gMp,   g_mp);
    uint32_t* gAuxp = nullptr; cudaGetSymbolAddress((void**)&gAuxp, g_auxp);
    float*    gLM   = nullptr; cudaGetSymbolAddress((void**)&gLM,   g_logitM);

    static cudaStream_t s1 = nullptr;
    static cudaEvent_t evFork = nullptr, evJoin = nullptr, evWtb = nullptr;
    if (!s1) {
        cudaStreamCreateWithFlags(&s1, cudaStreamNonBlocking);
        cudaEventCreateWithFlags(&evFork, cudaEventDisableTiming);
        cudaEventCreateWithFlags(&evJoin, cudaEventDisableTiming);
        cudaEventCreateWithFlags(&evWtb,  cudaEventDisableTiming);
        cudaFuncSetAttribute(conv_mma, cudaFuncAttributeMaxDynamicSharedMemorySize, SMEM_SZ);
    }

    // fork side stream off the main (capture) stream
    cudaEventRecord(evFork, 0);
    cudaStreamWaitEvent(s1, evFork, 0);

    // side stream: weights, geometry, aux construction
    wtb_kernel<<<(2 * 72 * 2 * 16 * 32 + 255) / 256, 256, 0, s1>>>(Wf);
    cudaEventRecord(evWtb, s1);
    geo_kernel<<<(NPIX + 255) / 256, 256, 0, s1>>>();
    aux_kernel<<<(32 * NPIX + 255) / 256, 256, 0, s1>>>(fb, fd, fu);
    cudaEventRecord(evJoin, s1);

    // main stream: pack m, wait for weights, main conv
    packm_kernel<<<(32 * NPIX + 255) / 256, 256>>>(m);
    cudaStreamWaitEvent(0, evWtb, 0);
    conv_mma<<<NPIX / 64, 256, SMEM_SZ>>>(gMp, bf, Wm, nullptr, gLM,
                                          nullptr, nullptr, nullptr);

    // join, then fused aux conv -> final output
    cudaStreamWaitEvent(0, evJoin, 0);
    conv_mma<<<NPIX / 64, 256, SMEM_SZ>>>(gAuxp, bf, Wm + CC, out, nullptr,
                                          m, gLM, bm);
}